// round 16
// baseline (speedup 1.0000x reference)
#include <cuda_runtime.h>
#include <cuda_fp16.h>
#include <cstdint>

// Problem dims
#define B_  32
#define I_  128
#define O_  256
#define E_  8
#define HW_ 3136   // 56*56
#define HH_ 56
#define WW_ 56
#define HID_ 32
#define PER_EXPERT (O_*I_*9)   // 294912

// Scratch (allocation-free: __device__ globals)
__device__ float g_pool[B_*I_];
__device__ float g_r[B_*E_];
__device__ float g_cb[B_*O_];
// x packed fp16: [b][s(8)][tig(4)][hw] uint2 = {h2(ic,ic+1), h2(ic+8,ic+9)}, ic=16s+2tig
__device__ uint2 g_xp[(size_t)B_*8*4*HW_];             // 25.7 MB
// weights packed fp16 as uint4 per (m16-tile row-pair):
// [b][ocg(4)][s(8)][toc(4)][kk(9)][g(8)][tig(4)] uint4 =
//   {h2(r,k01), h2(r,k89), h2(r+8,k01), h2(r+8,k89)},  r = toc*16+g
__device__ uint4 g_cw4[(size_t)B_*4*8*4*9*8*4];        // 18.9 MB

// ---------------------------------------------------------------------------
// helpers
// ---------------------------------------------------------------------------
__device__ __forceinline__ unsigned h2u(__half2 h) { return *(unsigned*)&h; }
__device__ __forceinline__ void mma_f16(float c[4],
                                        unsigned a0, unsigned a1, unsigned a2, unsigned a3,
                                        unsigned b0, unsigned b1) {
    asm("mma.sync.aligned.m16n8k16.row.col.f32.f16.f16.f32 "
        "{%0,%1,%2,%3}, {%4,%5,%6,%7}, {%8,%9}, {%0,%1,%2,%3};"
        : "+f"(c[0]), "+f"(c[1]), "+f"(c[2]), "+f"(c[3])
        : "r"(a0), "r"(a1), "r"(a2), "r"(a3), "r"(b0), "r"(b1));
}
__device__ __forceinline__ void cpa16(uint32_t dst, const void* src) {
    asm volatile("cp.async.cg.shared.global [%0], [%1], 16;" :: "r"(dst), "l"(src) : "memory");
}

// ---------------------------------------------------------------------------
// Kernel 0: repack x -> paired fp16 layout + fused global average pool.
// grid (32, B): blockIdx.x = s*4+tig. Channels c0,c0+1,c0+8,c0+9, c0=16s+2tig.
// ---------------------------------------------------------------------------
__global__ __launch_bounds__(256) void repack_kernel(const float* __restrict__ x)
{
    int st = blockIdx.x;
    int b  = blockIdx.y;
    int s  = st >> 2;
    int tg = st & 3;
    int c0 = s * 16 + tg * 2;
    int t  = threadIdx.x;

    const float2* p0 = (const float2*)(x + ((size_t)b * I_ + c0    ) * HW_);
    const float2* p1 = (const float2*)(x + ((size_t)b * I_ + c0 + 1) * HW_);
    const float2* p8 = (const float2*)(x + ((size_t)b * I_ + c0 + 8) * HW_);
    const float2* p9 = (const float2*)(x + ((size_t)b * I_ + c0 + 9) * HW_);
    uint4* op = (uint4*)(g_xp + ((size_t)(b * 8 + s) * 4 + tg) * HW_);

    float s0 = 0.f, s1 = 0.f, s8 = 0.f, s9 = 0.f;
    for (int j = t; j < HW_ / 2; j += 256) {
        float2 v0 = p0[j], v1 = p1[j], v8 = p8[j], v9 = p9[j];
        s0 += v0.x + v0.y; s1 += v1.x + v1.y;
        s8 += v8.x + v8.y; s9 += v9.x + v9.y;
        op[j] = make_uint4(
            h2u(__floats2half2_rn(v0.x, v1.x)), h2u(__floats2half2_rn(v8.x, v9.x)),
            h2u(__floats2half2_rn(v0.y, v1.y)), h2u(__floats2half2_rn(v8.y, v9.y)));
    }
    // reduce 4 sums across the block
    __shared__ float red[8][4];
    int lane = t & 31, warp = t >> 5;
    #pragma unroll
    for (int o = 16; o; o >>= 1) {
        s0 += __shfl_xor_sync(0xffffffffu, s0, o);
        s1 += __shfl_xor_sync(0xffffffffu, s1, o);
        s8 += __shfl_xor_sync(0xffffffffu, s8, o);
        s9 += __shfl_xor_sync(0xffffffffu, s9, o);
    }
    if (lane == 0) { red[warp][0] = s0; red[warp][1] = s1; red[warp][2] = s8; red[warp][3] = s9; }
    __syncthreads();
    if (t < 4) {
        float a = 0.f;
        #pragma unroll
        for (int w = 0; w < 8; w++) a += red[w][t];
        int c = c0 + ((t & 1) ? 1 : 0) + ((t & 2) ? 8 : 0);
        g_pool[b * I_ + c] = a * (1.0f / (float)HW_);
    }
}

// ---------------------------------------------------------------------------
// Kernel 1: routing MLP + softmax + combined bias. One block per sample.
// ---------------------------------------------------------------------------
__global__ __launch_bounds__(256) void mlp_kernel(
    const float* __restrict__ bias,
    const float* __restrict__ w1, const float* __restrict__ b1,
    const float* __restrict__ w2, const float* __restrict__ b2)
{
    int b = blockIdx.x;
    __shared__ float s_pool[I_];
    __shared__ float s_h[HID_];
    __shared__ float s_logit[E_];
    __shared__ float s_r[E_];

    int t = threadIdx.x;
    if (t < I_) s_pool[t] = g_pool[b * I_ + t];
    __syncthreads();

    if (t < HID_) {
        float s = b1[t];
        #pragma unroll 8
        for (int i = 0; i < I_; i++) s += s_pool[i] * w1[t * I_ + i];
        s_h[t] = fmaxf(s, 0.f);
    }
    __syncthreads();

    if (t < E_) {
        float s = b2[t];
        #pragma unroll
        for (int j = 0; j < HID_; j++) s += s_h[j] * w2[t * HID_ + j];
        s_logit[t] = s;
    }
    __syncthreads();

    if (t < E_) {
        float m = s_logit[0];
        #pragma unroll
        for (int e = 1; e < E_; e++) m = fmaxf(m, s_logit[e]);
        float den = 0.f;
        #pragma unroll
        for (int e = 0; e < E_; e++) den += expf(s_logit[e] - m);
        float rv = expf(s_logit[t] - m) / den;
        s_r[t] = rv;
        g_r[b * E_ + t] = rv;
    }
    __syncthreads();

    if (t < O_) {
        float s = 0.f;
        #pragma unroll
        for (int e = 0; e < E_; e++) s += s_r[e] * bias[e * O_ + t];
        g_cb[b * O_ + t] = s;
    }
}

// ---------------------------------------------------------------------------
// Kernel 2: combine weights -> pre-swizzled paired-fp16 uint4 layout.
// grid (O_, 4): block = (oc, group of 8 samples).
// ---------------------------------------------------------------------------
__global__ __launch_bounds__(256) void combine_kernel(const float* __restrict__ weight)
{
    int oc  = blockIdx.x;           // 0..255
    int bg  = blockIdx.y;           // 0..3 -> samples bg*8..bg*8+7
    int ocg = oc >> 6;
    int ocl = oc & 63;
    int toc = ocl >> 4;
    int rowin = ocl & 15;
    int g   = rowin & 7;
    int hi  = rowin >> 3;           // 0: .xy, 1: .zw of the uint4
    int t   = threadIdx.x;

    __shared__ float wsm[E_][I_ * 9];    // 36.9 KB
    __shared__ float rs[64];

    #pragma unroll
    for (int e = 0; e < E_; e++) {
        const float4* src = (const float4*)(weight + ((size_t)e * O_ + oc) * (I_ * 9));
        float4* dst = (float4*)wsm[e];
        for (int j = t; j < (I_ * 9) / 4; j += 256) dst[j] = src[j];
    }
    if (t < 64) rs[t] = g_r[bg * 64 + t];
    __syncthreads();

    #pragma unroll
    for (int i = 0; i < 2; i++) {
        int slot = t + 256 * i;          // (s8, kk9, tg4): 288 slots
        if (slot >= 288) break;
        int s   = slot / 36;
        int r36 = slot % 36;
        int kk  = r36 >> 2;
        int tg  = r36 & 3;
        int ic  = s * 16 + tg * 2;

        float w0[E_], w1v[E_], w8[E_], w9[E_];
        #pragma unroll
        for (int e = 0; e < E_; e++) {
            w0[e]  = wsm[e][ ic      * 9 + kk];
            w1v[e] = wsm[e][(ic + 1) * 9 + kk];
            w8[e]  = wsm[e][(ic + 8) * 9 + kk];
            w9[e]  = wsm[e][(ic + 9) * 9 + kk];
        }
        #pragma unroll 2
        for (int bb = 0; bb < 8; bb++) {
            int b = bg * 8 + bb;
            float a0 = 0.f, a1 = 0.f, a8 = 0.f, a9 = 0.f;
            #pragma unroll
            for (int e = 0; e < E_; e++) {
                float r = rs[bb * E_ + e];
                a0 = fmaf(r, w0[e],  a0);
                a1 = fmaf(r, w1v[e], a1);
                a8 = fmaf(r, w8[e],  a8);
                a9 = fmaf(r, w9[e],  a9);
            }
            // uint4 index inside slab [toc][kk][g][tg]; write half (uint2)
            size_t i4 = (((size_t)(b * 4 + ocg) * 8 + s) * 1152)
                      + (size_t)(toc * 288 + kk * 32 + g * 4 + tg);
            uint2* dst = (uint2*)((char*)(g_cw4 + i4) + hi * 8);
            *dst = make_uint2(h2u(__floats2half2_rn(a0, a1)),
                              h2u(__floats2half2_rn(a8, a9)));
        }
    }
}

// ---------------------------------------------------------------------------
// Kernel 3: fp16 m16n8k16 implicit-GEMM conv, async double-buffered.
// Block: (b, 64 oc, 4 rows x 56 cols). 8 warps = 2 M x 4 N. 8 K-steps of 16 ic.
// A fragments: one LDS.128 per m16 tile per kk (uint4 layout).
// x slice stride 372 uint2 (≡4 mod 16) -> LDS.64 conflict-free.
// ---------------------------------------------------------------------------
#define XSLICE 372              // uint2 per tig slice (6 rows * 60, padded)
#define XBUF   1488             // 4 slices (uint2)
#define WBUF   2304             // uint2-equivalents (= 1152 uint4 = 18432 B)
#define XSLAB_BYTES (4*HW_*8)   // per (b,s) x slab: 100352 B
#define WSLAB_BYTES (WBUF*8)    // 18432 B

__global__ __launch_bounds__(256, 2) void conv_kernel(float* __restrict__ out)
{
    extern __shared__ uint2 dsm[];
    uint2* xsb[2] = { dsm, dsm + XBUF };
    const uint4* wsb4[2] = { (const uint4*)(dsm + 2 * XBUF),
                             (const uint4*)(dsm + 2 * XBUF + WBUF) };
    uint32_t smem_u32 = (uint32_t)__cvta_generic_to_shared(dsm);

    int b   = blockIdx.z;
    int ocg = blockIdx.y;
    int oc0 = ocg * 64;
    int r0  = blockIdx.x * 4;

    int t     = threadIdx.x;
    int lane  = t & 31;
    int warp  = t >> 5;
    int warpM = warp >> 2;
    int warpN = warp & 3;
    int gid   = lane >> 2;
    int tig   = lane & 3;

    // ---- zero x buffers (halo stays zero) ----
    for (int i = t; i < 2 * XBUF; i += 256) dsm[i] = make_uint2(0u, 0u);

    // ---- per-thread cp.async descriptors (step-invariant) ----
    uint32_t xdst[3]; uint32_t xsrc[3]; bool xval[3];
    #pragma unroll
    for (int i = 0; i < 3; i++) {
        int ch  = t + 256 * i;
        bool in = (ch < 672);
        int c   = in ? ch : 0;
        int tg  = c / 168;
        int rem = c % 168;
        int rr  = rem / 28;
        int c16 = rem % 28;
        int gh  = r0 - 1 + rr;
        xval[i] = in && (gh >= 0) && (gh < HH_);
        xsrc[i] = (uint32_t)((tg * HW_ + gh * WW_ + c16 * 2) * 8);
        xdst[i] = (uint32_t)((tg * XSLICE + rr * 60 + 2 + c16 * 2) * 8);
    }
    const char* xsrc_base = (const char*)(g_xp + (size_t)b * 8 * 4 * HW_);
    const char* wsrc_base = (const char*)(g_cw4 + (size_t)(b * 4 + ocg) * 8 * 1152);

    __syncthreads();

    // ---- prologue: stage step 0 into buffer 0 ----
    {
        #pragma unroll
        for (int i = 0; i < 3; i++)
            if (xval[i]) cpa16(smem_u32 + xdst[i], xsrc_base + xsrc[i]);
        uint32_t wdst0 = smem_u32 + 2 * XBUF * 8;
        #pragma unroll
        for (int i = 0; i < 5; i++) {
            int ch = t + 256 * i;
            if (ch < 1152) cpa16(wdst0 + ch * 16, wsrc_base + ch * 16);
        }
        asm volatile("cp.async.commit_group;" ::: "memory");
        asm volatile("cp.async.wait_group 0;" ::: "memory");
    }
    __syncthreads();

    float acc0[7][4], acc1[7][4];
    #pragma unroll
    for (int f = 0; f < 7; f++)
        #pragma unroll
        for (int q = 0; q < 4; q++) { acc0[f][q] = 0.f; acc1[f][q] = 0.f; }

    for (int s = 0; s < 8; s++) {
        int cur = s & 1, nxt = cur ^ 1;

        if (s < 7) {
            const char* xp = xsrc_base + (size_t)(s + 1) * XSLAB_BYTES;
            uint32_t xb_u = smem_u32 + nxt * XBUF * 8;
            #pragma unroll
            for (int i = 0; i < 3; i++)
                if (xval[i]) cpa16(xb_u + xdst[i], xp + xsrc[i]);
            const char* wp = wsrc_base + (size_t)(s + 1) * WSLAB_BYTES;
            uint32_t wb_u = smem_u32 + (2 * XBUF + nxt * WBUF) * 8;
            #pragma unroll
            for (int i = 0; i < 5; i++) {
                int ch = t + 256 * i;
                if (ch < 1152) cpa16(wb_u + ch * 16, wp + ch * 16);
            }
        }
        asm volatile("cp.async.commit_group;" ::: "memory");

        const uint2* xbase = xsb[cur] + tig * XSLICE + warpN * 60 + gid + 1;
        // A: per warp 2 m16 tiles: toc = warpM*2, warpM*2+1
        const uint4* wbase = wsb4[cur] + (warpM * 2) * 288 + gid * 4 + tig;

        #pragma unroll
        for (int kh = 0; kh < 3; kh++) {
            #pragma unroll
            for (int kw = 0; kw < 3; kw++) {
                int kk = kh * 3 + kw;
                uint4 aT0 = wbase[kk * 32];
                uint4 aT1 = wbase[kk * 32 + 288];
                const uint2* bp = xbase + kh * 60 + kw;
                #pragma unroll
                for (int f = 0; f < 7; f++) {
                    uint2 bv = bp[f * 8];
                    mma_f16(acc0[f], aT0.x, aT0.z, aT0.y, aT0.w, bv.x, bv.y);
                    mma_f16(acc1[f], aT1.x, aT1.z, aT1.y, aT1.w, bv.x, bv.y);
                }
            }
        }

        asm volatile("cp.async.wait_group 0;" ::: "memory");
        __syncthreads();
    }

    // ---- epilogue ----
    int h = r0 + warpN;
    #pragma unroll
    for (int m = 0; m < 2; m++) {
        int ocA = oc0 + (warpM * 2 + m) * 16 + gid;
        int ocB = ocA + 8;
        float cbA = g_cb[b * O_ + ocA];
        float cbB = g_cb[b * O_ + ocB];
        float* outA = out + ((size_t)b * O_ + ocA) * HW_ + h * WW_;
        float* outB = out + ((size_t)b * O_ + ocB) * HW_ + h * WW_;
        float (*acc)[4] = m ? acc1 : acc0;
        #pragma unroll
        for (int f = 0; f < 7; f++) {
            int col = f * 8 + tig * 2;
            *(float2*)(outA + col) = make_float2(acc[f][0] + cbA, acc[f][1] + cbA);
            *(float2*)(outB + col) = make_float2(acc[f][2] + cbB, acc[f][3] + cbB);
        }
    }
}

// ---------------------------------------------------------------------------
extern "C" void kernel_launch(void* const* d_in, const int* in_sizes, int n_in,
                              void* d_out, int out_size)
{
    const float* x      = (const float*)d_in[0];
    const float* weight = (const float*)d_in[1];
    const float* bias   = (const float*)d_in[2];
    const float* w1     = (const float*)d_in[3];
    const float* b1     = (const float*)d_in[4];
    const float* w2     = (const float*)d_in[5];
    const float* b2     = (const float*)d_in[6];
    float* out = (float*)d_out;

    repack_kernel<<<dim3(32, B_), 256>>>(x);
    mlp_kernel<<<B_, 256>>>(bias, w1, b1, w2, b2);
    combine_kernel<<<dim3(O_, 4), 256>>>(weight);

    int smem_bytes = (2 * XBUF + 2 * WBUF) * 8;   // 60672
    cudaFuncSetAttribute(conv_kernel, cudaFuncAttributeMaxDynamicSharedMemorySize, smem_bytes);
    dim3 grid(HH_ / 4, O_ / 64, B_);              // (14, 4, 32)
    conv_kernel<<<grid, 256, smem_bytes>>>(out);
}